// round 7
// baseline (speedup 1.0000x reference)
#include <cuda_runtime.h>
#include <cuda_bf16.h>
#include <cstdint>

#define BB 1024
#define AA 200
#define DD 128
#define NH 8
#define DH 16
#define INV_SQRT_D 0.08838834764831845f
#define NEG_BIG (-1e30f)

// ---------------- scratch (device globals; no runtime allocation) -------------
__device__ __nv_bfloat16 g_Q [(size_t)BB*AA*DD];   // queries * 0.25, row-major [b][i][d]
__device__ __nv_bfloat16 g_KT[(size_t)BB*DD*AA];   // gK transposed [b][d][a]
__device__ __nv_bfloat16 g_VT[(size_t)BB*DD*AA];   // gV transposed [b][d][a]
__device__ __nv_bfloat16 g_LK[(size_t)BB*AA*DD];   // logit_K row-major [b][a][j]
__device__ __nv_bfloat16 g_L2T[(size_t)BB*DD*AA];  // logitK2 transposed [b][d][a]
__device__ float g_FC[BB*DD];                      // fixed context [b][d]

// ---------------- helpers ------------------------------------------------------
__device__ __forceinline__ float2 upk(uint32_t u){
    float2 r;
    r.x = __uint_as_float(u << 16);
    r.y = __uint_as_float(u & 0xffff0000u);
    return r;
}
__device__ __forceinline__ uint16_t f2b(float x){
    return __bfloat16_as_ushort(__float2bfloat16(x));
}
__device__ __forceinline__ uint32_t pk2(float a, float b){
    return (uint32_t)f2b(a) | ((uint32_t)f2b(b) << 16);
}
__device__ __forceinline__ float wredmax(float v){
    #pragma unroll
    for (int o = 16; o; o >>= 1) v = fmaxf(v, __shfl_xor_sync(0xffffffffu, v, o));
    return v;
}
__device__ __forceinline__ float wredsum(float v){
    #pragma unroll
    for (int o = 16; o; o >>= 1) v += __shfl_xor_sync(0xffffffffu, v, o);
    return v;
}

// ---------------- kernel 1: fixed context --------------------------------------
__global__ void k_fixed(const float* __restrict__ agent, const float* __restrict__ Wf){
    int b = blockIdx.x, j = threadIdx.x;
    __shared__ float ge[DD];
    const float* row = agent + (size_t)b*AA*DD;
    float s = 0.f;
    #pragma unroll 4
    for (int a = 0; a < AA; a++) s += row[a*DD + j];
    ge[j] = s * (1.0f/AA);
    __syncthreads();
    float acc = 0.f;
    #pragma unroll 4
    for (int d = 0; d < DD; d++) acc = fmaf(ge[d], Wf[d*DD + j], acc);
    g_FC[b*DD + j] = acc;
}

// ---------------- kernel 2: proj = X @ W_node -> gK^T, gV^T, logit_K ----------
#define PROJ_SMEM (51200 + 384*130*2)
__global__ void __launch_bounds__(256,1) k_proj(const float* __restrict__ agent,
                                                const float* __restrict__ Wn){
    extern __shared__ char sm[];
    uint16_t* sX = (uint16_t*)sm;              // [200][128] bf16
    uint16_t* sW = (uint16_t*)(sm + 51200);    // W^T padded [384][130]
    int b = blockIdx.x, tid = threadIdx.x;
    const float* Xg = agent + (size_t)b*AA*DD;
    for (int idx = tid; idx < AA*DD; idx += 256) sX[idx] = f2b(Xg[idx]);
    for (int idx = tid; idx < DD*384; idx += 256){
        int k = idx / 384, j = idx % 384;
        sW[j*130 + k] = f2b(Wn[idx]);
    }
    __syncthreads();
    int tx = tid & 127, ty = tid >> 7;
    __nv_bfloat16* KT = g_KT + (size_t)b*DD*AA;
    __nv_bfloat16* VT = g_VT + (size_t)b*DD*AA;
    __nv_bfloat16* LK = g_LK + (size_t)b*AA*DD;
    const uint32_t* w0 = (const uint32_t*)(sW + (tx      )*130);
    const uint32_t* w1 = (const uint32_t*)(sW + (tx + 128)*130);
    const uint32_t* w2 = (const uint32_t*)(sW + (tx + 256)*130);
    for (int rr = 0; rr < 13; rr++){
        int r0 = rr*16 + ty*8;
        if (r0 >= AA) break;
        float acc[8][3];
        #pragma unroll
        for (int u = 0; u < 8; u++){ acc[u][0]=0.f; acc[u][1]=0.f; acc[u][2]=0.f; }
        #pragma unroll 4
        for (int kk = 0; kk < 64; kk++){
            float2 f0 = upk(w0[kk]);
            float2 f1 = upk(w1[kk]);
            float2 f2 = upk(w2[kk]);
            #pragma unroll
            for (int u = 0; u < 8; u++){
                float2 x = upk(((const uint32_t*)(sX + (r0+u)*DD))[kk]);
                acc[u][0] = fmaf(x.x, f0.x, fmaf(x.y, f0.y, acc[u][0]));
                acc[u][1] = fmaf(x.x, f1.x, fmaf(x.y, f1.y, acc[u][1]));
                acc[u][2] = fmaf(x.x, f2.x, fmaf(x.y, f2.y, acc[u][2]));
            }
        }
        uint4 ok = make_uint4(pk2(acc[0][0],acc[1][0]), pk2(acc[2][0],acc[3][0]),
                              pk2(acc[4][0],acc[5][0]), pk2(acc[6][0],acc[7][0]));
        uint4 ov = make_uint4(pk2(acc[0][1],acc[1][1]), pk2(acc[2][1],acc[3][1]),
                              pk2(acc[4][1],acc[5][1]), pk2(acc[6][1],acc[7][1]));
        *(uint4*)(KT + tx*AA + r0) = ok;
        *(uint4*)(VT + tx*AA + r0) = ov;
        #pragma unroll
        for (int u = 0; u < 8; u++) LK[(r0+u)*DD + tx] = __float2bfloat16(acc[u][2]);
    }
}

// ---------------- kernel 3: queries (pre-scaled by 1/sqrt(dh)=0.25) -----------
#define QRY_SMEM (51200 + 128*130*2 + 1024)
__global__ void __launch_bounds__(256,1) k_query(const float* __restrict__ agent,
                                                 const int* __restrict__ act_g,
                                                 const float* __restrict__ Wp,
                                                 const float* __restrict__ Ws){
    extern __shared__ char sm[];
    uint16_t* sX  = (uint16_t*)sm;                     // step contexts [200][128]
    uint16_t* sW  = (uint16_t*)(sm + 51200);           // W_step^T [128][130]
    int*      sAct = (int*)(sm + 51200 + 33280);
    int b = blockIdx.x, tid = threadIdx.x;
    if (tid < AA) sAct[tid] = act_g[b*AA + tid];
    for (int idx = tid; idx < DD*DD; idx += 256){
        int k = idx >> 7, j = idx & 127;
        sW[j*130 + k] = f2b(Ws[idx]);
    }
    __syncthreads();
    for (int idx = tid; idx < AA*DD; idx += 256){
        int i = idx >> 7, d = idx & 127;
        float v = (i == 0) ? Wp[d] : agent[((size_t)b*AA + sAct[i-1])*DD + d];
        sX[idx] = f2b(v);
    }
    __syncthreads();
    int tx = tid & 127, ty = tid >> 7;
    float fc = g_FC[b*DD + tx];
    __nv_bfloat16* Qo = g_Q + (size_t)b*AA*DD;
    const uint32_t* wrow = (const uint32_t*)(sW + tx*130);
    for (int rr = 0; rr < 13; rr++){
        int r0 = rr*16 + ty*8;
        if (r0 >= AA) break;
        float acc[8] = {0,0,0,0,0,0,0,0};
        #pragma unroll 4
        for (int kk = 0; kk < 64; kk++){
            float2 wv = upk(wrow[kk]);
            #pragma unroll
            for (int u = 0; u < 8; u++){
                float2 x = upk(((const uint32_t*)(sX + (r0+u)*DD))[kk]);
                acc[u] = fmaf(x.x, wv.x, fmaf(x.y, wv.y, acc[u]));
            }
        }
        #pragma unroll
        for (int u = 0; u < 8; u++)
            Qo[(r0+u)*DD + tx] = __float2bfloat16((fc + acc[u]) * 0.25f);
    }
}

// ---------------- kernel 4: logitK2^T = (logit_K @ W_out^T)^T -----------------
#define LK2_SMEM (51200 + 128*130*2)
__global__ void __launch_bounds__(256,1) k_lk2(const float* __restrict__ Wo){
    extern __shared__ char sm[];
    uint16_t* sX = (uint16_t*)sm;              // logit_K rows [200][128]
    uint16_t* sW = (uint16_t*)(sm + 51200);    // W_out rows padded [128][130]
    int b = blockIdx.x, tid = threadIdx.x;
    const uint4* src = (const uint4*)(g_LK + (size_t)b*AA*DD);
    uint4* dstX = (uint4*)sX;
    for (int idx = tid; idx < AA*DD/8; idx += 256) dstX[idx] = src[idx];
    for (int idx = tid; idx < DD*DD; idx += 256){
        int d = idx >> 7, j = idx & 127;
        sW[d*130 + j] = f2b(Wo[idx]);
    }
    __syncthreads();
    int tx = tid & 127, ty = tid >> 7;
    __nv_bfloat16* L2 = g_L2T + (size_t)b*DD*AA;
    const uint32_t* wrow = (const uint32_t*)(sW + tx*130);
    for (int rr = 0; rr < 13; rr++){
        int r0 = rr*16 + ty*8;
        if (r0 >= AA) break;
        float acc[8] = {0,0,0,0,0,0,0,0};
        #pragma unroll 4
        for (int kk = 0; kk < 64; kk++){
            float2 wv = upk(wrow[kk]);
            #pragma unroll
            for (int u = 0; u < 8; u++){
                float2 x = upk(((const uint32_t*)(sX + (r0+u)*DD))[kk]);
                acc[u] = fmaf(x.x, wv.x, fmaf(x.y, wv.y, acc[u]));
            }
        }
        *(uint4*)(L2 + tx*AA + r0) =
            make_uint4(pk2(acc[0],acc[1]), pk2(acc[2],acc[3]),
                       pk2(acc[4],acc[5]), pk2(acc[6],acc[7]));
    }
}

// ---------------- kernel 5: decode (all 200 steps per batch row) --------------
#define DEC_SQ   0
#define DEC_SK   51200
#define DEC_SV   102400
#define DEC_SL   153600
#define DEC_HD   204928          // 128B OOB pad before this
#define DEC_POS  213120
#define DEC_ACT  213376
#define DEC_WLP  214176
#define DEC_SMEM 214272

__global__ void __launch_bounds__(512,1) k_decode(const int* __restrict__ act_g,
                                                  float* __restrict__ out, int mode){
    extern __shared__ char sm[];
    uint16_t* sQ  = (uint16_t*)(sm + DEC_SQ);
    uint16_t* sK  = (uint16_t*)(sm + DEC_SK);
    uint16_t* sV  = (uint16_t*)(sm + DEC_SV);
    uint16_t* sL  = (uint16_t*)(sm + DEC_SL);
    float*    sHd = (float*)(sm + DEC_HD);     // [16 warps][128]
    uint8_t*  sPos= (uint8_t*)(sm + DEC_POS);
    int*      sAct= (int*)(sm + DEC_ACT);
    float*    sWlp= (float*)(sm + DEC_WLP);
    int b = blockIdx.x, tid = threadIdx.x;
    int w = tid >> 5, l = tid & 31;

    {
        const uint4* q4 = (const uint4*)(g_Q   + (size_t)b*AA*DD);
        const uint4* k4 = (const uint4*)(g_KT  + (size_t)b*DD*AA);
        const uint4* v4 = (const uint4*)(g_VT  + (size_t)b*DD*AA);
        const uint4* l4 = (const uint4*)(g_L2T + (size_t)b*DD*AA);
        uint4* dq = (uint4*)sQ; uint4* dk = (uint4*)sK;
        uint4* dv = (uint4*)sV; uint4* dl = (uint4*)sL;
        for (int idx = tid; idx < 3200; idx += 512){
            dq[idx] = q4[idx]; dk[idx] = k4[idx];
            dv[idx] = v4[idx]; dl[idx] = l4[idx];
        }
        if (tid < AA) sAct[tid] = act_g[b*AA + tid];
    }
    __syncthreads();
    if (tid < AA) sPos[sAct[tid]] = (uint8_t)tid;
    __syncthreads();

    float lp_acc = 0.f;
    for (int i = w; i < AA; i += 16){
        int act_i = sAct[i];
        unsigned dead = 0, sel = 0;
        #pragma unroll
        for (int s = 0; s < 8; s++){
            int a = ((s >> 1) << 6) + 2*l + (s & 1);
            bool dd = (a >= AA) || ((int)sPos[a & 255] < i);
            if (dd) dead |= 1u << s;
            if (a == act_i) sel |= 1u << s;
        }
        const uint16_t* qrow = sQ + i*DD;

        #pragma unroll 1
        for (int h = 0; h < NH; h++){
            float c[8] = {0,0,0,0,0,0,0,0};
            #pragma unroll
            for (int d = 0; d < DH; d++){
                float q = __uint_as_float(((uint32_t)qrow[h*DH + d]) << 16);
                const uint32_t* krow = (const uint32_t*)(sK + (h*DH + d)*AA) + l;
                #pragma unroll
                for (int t = 0; t < 4; t++){
                    float2 kf = upk(krow[t*32]);
                    c[2*t]   = fmaf(q, kf.x, c[2*t]);
                    c[2*t+1] = fmaf(q, kf.y, c[2*t+1]);
                }
            }
            float m = NEG_BIG;
            #pragma unroll
            for (int s = 0; s < 8; s++){
                float cm = ((dead >> s) & 1) ? NEG_BIG : c[s];
                c[s] = cm; m = fmaxf(m, cm);
            }
            m = wredmax(m);
            float ssum = 0.f, wt[8];
            #pragma unroll
            for (int s = 0; s < 8; s++){
                float e = ((dead >> s) & 1) ? 0.f : __expf(c[s] - m);
                wt[s] = e; ssum += e;
            }
            ssum = wredsum(ssum);
            float inv = 1.0f / ssum;
            #pragma unroll
            for (int d = 0; d < DH; d++){
                const uint32_t* vrow = (const uint32_t*)(sV + (h*DH + d)*AA) + l;
                float p = 0.f;
                #pragma unroll
                for (int t = 0; t < 4; t++){
                    float2 vf = upk(vrow[t*32]);
                    p = fmaf(wt[2*t],   vf.x, p);
                    p = fmaf(wt[2*t+1], vf.y, p);
                }
                p = wredsum(p);
                if (l == 0) sHd[w*DD + h*DH + d] = p * inv;
            }
        }
        __syncwarp();

        float lg[8] = {0,0,0,0,0,0,0,0};
        #pragma unroll 4
        for (int d = 0; d < DD; d++){
            float hd = sHd[w*DD + d];
            const uint32_t* lrow = (const uint32_t*)(sL + d*AA) + l;
            #pragma unroll
            for (int t = 0; t < 4; t++){
                float2 lf = upk(lrow[t*32]);
                lg[2*t]   = fmaf(hd, lf.x, lg[2*t]);
                lg[2*t+1] = fmaf(hd, lf.y, lg[2*t+1]);
            }
        }
        __syncwarp();   // protect sHd region from next iteration's writes

        float m2 = NEG_BIG, selv = 0.f;
        #pragma unroll
        for (int s = 0; s < 8; s++){
            float x = tanhf(lg[s] * INV_SQRT_D) * 10.0f;
            x = ((dead >> s) & 1) ? NEG_BIG : x;
            if ((sel >> s) & 1) selv = x;
            lg[s] = x;
            m2 = fmaxf(m2, x);
        }
        m2 = wredmax(m2);
        float es = 0.f;
        #pragma unroll
        for (int s = 0; s < 8; s++)
            es += ((dead >> s) & 1) ? 0.f : __expf(lg[s] - m2);
        es   = wredsum(es);
        selv = wredsum(selv);
        lp_acc += selv - m2 - __logf(es);
    }

    if (l == 0) sWlp[w] = lp_acc;
    __syncthreads();
    float* lp_out = mode ? (out + BB*AA) : out;
    if (tid == 0){
        float t = 0.f;
        #pragma unroll
        for (int k = 0; k < 16; k++) t += sWlp[k];
        lp_out[b] = t;
    }
    if (mode){
        for (int idx = tid; idx < AA; idx += 512)
            out[b*AA + idx] = (float)sAct[idx];
    }
}

// ---------------- launch -------------------------------------------------------
extern "C" void kernel_launch(void* const* d_in, const int* in_sizes, int n_in,
                              void* d_out, int out_size){
    const float* agent = (const float*)d_in[0];
    const int*   act   = (const int*)d_in[1];
    const float* Wp    = (const float*)d_in[2];
    const float* Wn    = (const float*)d_in[3];
    const float* Wf    = (const float*)d_in[4];
    const float* Ws    = (const float*)d_in[5];
    const float* Wo    = (const float*)d_in[6];
    float* out = (float*)d_out;

    cudaFuncSetAttribute(k_proj,   cudaFuncAttributeMaxDynamicSharedMemorySize, PROJ_SMEM);
    cudaFuncSetAttribute(k_query,  cudaFuncAttributeMaxDynamicSharedMemorySize, QRY_SMEM);
    cudaFuncSetAttribute(k_lk2,    cudaFuncAttributeMaxDynamicSharedMemorySize, LK2_SMEM);
    cudaFuncSetAttribute(k_decode, cudaFuncAttributeMaxDynamicSharedMemorySize, DEC_SMEM);

    k_fixed <<<BB, 128>>>(agent, Wf);
    k_proj  <<<BB, 256, PROJ_SMEM>>>(agent, Wn);
    k_query <<<BB, 256, QRY_SMEM>>>(agent, act, Wp, Ws);
    k_lk2   <<<BB, 256, LK2_SMEM>>>(Wo);

    int mode = (out_size >= BB*AA) ? 1 : 0;
    k_decode<<<BB, 512, DEC_SMEM>>>(act, out, mode);
}

// round 8
// speedup vs baseline: 1.4666x; 1.4666x over previous
#include <cuda_runtime.h>
#include <cuda_bf16.h>
#include <cstdint>

#define BB 1024
#define AA 200
#define DD 128
#define NH 8
#define DH 16
#define INV_SQRT_D 0.08838834764831845f
#define NEG_BIG (-1e30f)

// ---------------- scratch (device globals; no runtime allocation) -------------
__device__ __nv_bfloat16 g_Q [(size_t)BB*AA*DD];   // queries * 0.25, row-major [b][i][d]
__device__ __nv_bfloat16 g_K [(size_t)BB*AA*DD];   // gK row-major [b][a][d]
__device__ __nv_bfloat16 g_VT[(size_t)BB*DD*AA];   // gV transposed [b][d][a]
__device__ __nv_bfloat16 g_LK[(size_t)BB*AA*DD];   // logit_K row-major [b][a][j]
__device__ __nv_bfloat16 g_L2[(size_t)BB*AA*DD];   // logitK2 row-major [b][a][d]
__device__ float g_FC[BB*DD];                      // fixed context [b][d]

// ---------------- helpers ------------------------------------------------------
__device__ __forceinline__ float2 upk(uint32_t u){
    float2 r;
    r.x = __uint_as_float(u << 16);
    r.y = __uint_as_float(u & 0xffff0000u);
    return r;
}
__device__ __forceinline__ uint16_t f2b(float x){
    return __bfloat16_as_ushort(__float2bfloat16(x));
}
__device__ __forceinline__ uint32_t pk2(float a, float b){
    return (uint32_t)f2b(a) | ((uint32_t)f2b(b) << 16);
}
__device__ __forceinline__ float wredsum(float v){
    #pragma unroll
    for (int o = 16; o; o >>= 1) v += __shfl_xor_sync(0xffffffffu, v, o);
    return v;
}
__device__ __forceinline__ float qredmax(float v){
    v = fmaxf(v, __shfl_xor_sync(0xffffffffu, v, 1));
    v = fmaxf(v, __shfl_xor_sync(0xffffffffu, v, 2));
    return v;
}
__device__ __forceinline__ float qredsum(float v){
    v += __shfl_xor_sync(0xffffffffu, v, 1);
    v += __shfl_xor_sync(0xffffffffu, v, 2);
    return v;
}
__device__ __forceinline__ void mma16816(float* d, const uint32_t* a, const uint32_t* b){
    asm volatile(
      "mma.sync.aligned.m16n8k16.row.col.f32.bf16.bf16.f32 "
      "{%0,%1,%2,%3}, {%4,%5,%6,%7}, {%8,%9}, {%0,%1,%2,%3};\n"
      : "+f"(d[0]), "+f"(d[1]), "+f"(d[2]), "+f"(d[3])
      : "r"(a[0]), "r"(a[1]), "r"(a[2]), "r"(a[3]), "r"(b[0]), "r"(b[1]));
}

// ---------------- kernel 1: fixed context --------------------------------------
__global__ void k_fixed(const float* __restrict__ agent, const float* __restrict__ Wf){
    int b = blockIdx.x, j = threadIdx.x;
    __shared__ float ge[DD];
    const float* row = agent + (size_t)b*AA*DD;
    float s = 0.f;
    #pragma unroll 4
    for (int a = 0; a < AA; a++) s += row[a*DD + j];
    ge[j] = s * (1.0f/AA);
    __syncthreads();
    float acc = 0.f;
    #pragma unroll 4
    for (int d = 0; d < DD; d++) acc = fmaf(ge[d], Wf[d*DD + j], acc);
    g_FC[b*DD + j] = acc;
}

// ---------------- kernel 2: proj = X @ W_node -> gK, gV^T, logit_K -------------
#define PROJ_SMEM (51200 + 384*130*2)
__global__ void __launch_bounds__(256,1) k_proj(const float* __restrict__ agent,
                                                const float* __restrict__ Wn){
    extern __shared__ char sm[];
    uint16_t* sX = (uint16_t*)sm;              // [200][128] bf16
    uint16_t* sW = (uint16_t*)(sm + 51200);    // W^T padded [384][130]
    int b = blockIdx.x, tid = threadIdx.x;
    const float* Xg = agent + (size_t)b*AA*DD;
    for (int idx = tid; idx < AA*DD; idx += 256) sX[idx] = f2b(Xg[idx]);
    for (int idx = tid; idx < DD*384; idx += 256){
        int k = idx / 384, j = idx % 384;
        sW[j*130 + k] = f2b(Wn[idx]);
    }
    __syncthreads();
    int tx = tid & 127, ty = tid >> 7;
    __nv_bfloat16* Kr = g_K  + (size_t)b*AA*DD;
    __nv_bfloat16* VT = g_VT + (size_t)b*DD*AA;
    __nv_bfloat16* LK = g_LK + (size_t)b*AA*DD;
    const uint32_t* w0 = (const uint32_t*)(sW + (tx      )*130);
    const uint32_t* w1 = (const uint32_t*)(sW + (tx + 128)*130);
    const uint32_t* w2 = (const uint32_t*)(sW + (tx + 256)*130);
    for (int rr = 0; rr < 13; rr++){
        int r0 = rr*16 + ty*8;
        if (r0 >= AA) break;
        float acc[8][3];
        #pragma unroll
        for (int u = 0; u < 8; u++){ acc[u][0]=0.f; acc[u][1]=0.f; acc[u][2]=0.f; }
        #pragma unroll 4
        for (int kk = 0; kk < 64; kk++){
            float2 f0 = upk(w0[kk]);
            float2 f1 = upk(w1[kk]);
            float2 f2 = upk(w2[kk]);
            #pragma unroll
            for (int u = 0; u < 8; u++){
                float2 x = upk(((const uint32_t*)(sX + (r0+u)*DD))[kk]);
                acc[u][0] = fmaf(x.x, f0.x, fmaf(x.y, f0.y, acc[u][0]));
                acc[u][1] = fmaf(x.x, f1.x, fmaf(x.y, f1.y, acc[u][1]));
                acc[u][2] = fmaf(x.x, f2.x, fmaf(x.y, f2.y, acc[u][2]));
            }
        }
        uint4 ov = make_uint4(pk2(acc[0][1],acc[1][1]), pk2(acc[2][1],acc[3][1]),
                              pk2(acc[4][1],acc[5][1]), pk2(acc[6][1],acc[7][1]));
        *(uint4*)(VT + tx*AA + r0) = ov;
        #pragma unroll
        for (int u = 0; u < 8; u++){
            Kr[(r0+u)*DD + tx] = __float2bfloat16(acc[u][0]);
            LK[(r0+u)*DD + tx] = __float2bfloat16(acc[u][2]);
        }
    }
}

// ---------------- kernel 3: queries (pre-scaled by 1/sqrt(dh)=0.25) -----------
#define QRY_SMEM (51200 + 128*130*2 + 1024)
__global__ void __launch_bounds__(256,1) k_query(const float* __restrict__ agent,
                                                 const int* __restrict__ act_g,
                                                 const float* __restrict__ Wp,
                                                 const float* __restrict__ Ws){
    extern __shared__ char sm[];
    uint16_t* sX  = (uint16_t*)sm;                     // step contexts [200][128]
    uint16_t* sW  = (uint16_t*)(sm + 51200);           // W_step^T [128][130]
    int*      sAct = (int*)(sm + 51200 + 33280);
    int b = blockIdx.x, tid = threadIdx.x;
    if (tid < AA) sAct[tid] = act_g[b*AA + tid];
    for (int idx = tid; idx < DD*DD; idx += 256){
        int k = idx >> 7, j = idx & 127;
        sW[j*130 + k] = f2b(Ws[idx]);
    }
    __syncthreads();
    for (int idx = tid; idx < AA*DD; idx += 256){
        int i = idx >> 7, d = idx & 127;
        float v = (i == 0) ? Wp[d] : agent[((size_t)b*AA + sAct[i-1])*DD + d];
        sX[idx] = f2b(v);
    }
    __syncthreads();
    int tx = tid & 127, ty = tid >> 7;
    float fc = g_FC[b*DD + tx];
    __nv_bfloat16* Qo = g_Q + (size_t)b*AA*DD;
    const uint32_t* wrow = (const uint32_t*)(sW + tx*130);
    for (int rr = 0; rr < 13; rr++){
        int r0 = rr*16 + ty*8;
        if (r0 >= AA) break;
        float acc[8] = {0,0,0,0,0,0,0,0};
        #pragma unroll 4
        for (int kk = 0; kk < 64; kk++){
            float2 wv = upk(wrow[kk]);
            #pragma unroll
            for (int u = 0; u < 8; u++){
                float2 x = upk(((const uint32_t*)(sX + (r0+u)*DD))[kk]);
                acc[u] = fmaf(x.x, wv.x, fmaf(x.y, wv.y, acc[u]));
            }
        }
        #pragma unroll
        for (int u = 0; u < 8; u++)
            Qo[(r0+u)*DD + tx] = __float2bfloat16((fc + acc[u]) * 0.25f);
    }
}

// ---------------- kernel 4: logitK2[a][d] = sum_j LK[a][j] * Wo[d][j] ----------
#define LK2_SMEM (51200 + 128*130*2)
__global__ void __launch_bounds__(256,1) k_lk2(const float* __restrict__ Wo){
    extern __shared__ char sm[];
    uint16_t* sX = (uint16_t*)sm;              // logit_K rows [200][128]
    uint16_t* sW = (uint16_t*)(sm + 51200);    // W_out rows padded [128][130]
    int b = blockIdx.x, tid = threadIdx.x;
    const uint4* src = (const uint4*)(g_LK + (size_t)b*AA*DD);
    uint4* dstX = (uint4*)sX;
    for (int idx = tid; idx < AA*DD/8; idx += 256) dstX[idx] = src[idx];
    for (int idx = tid; idx < DD*DD; idx += 256){
        int d = idx >> 7, j = idx & 127;
        sW[d*130 + j] = f2b(Wo[idx]);
    }
    __syncthreads();
    int tx = tid & 127, ty = tid >> 7;
    __nv_bfloat16* L2 = g_L2 + (size_t)b*AA*DD;
    const uint32_t* wrow = (const uint32_t*)(sW + tx*130);
    for (int rr = 0; rr < 13; rr++){
        int r0 = rr*16 + ty*8;
        if (r0 >= AA) break;
        float acc[8] = {0,0,0,0,0,0,0,0};
        #pragma unroll 4
        for (int kk = 0; kk < 64; kk++){
            float2 wv = upk(wrow[kk]);
            #pragma unroll
            for (int u = 0; u < 8; u++){
                float2 x = upk(((const uint32_t*)(sX + (r0+u)*DD))[kk]);
                acc[u] = fmaf(x.x, wv.x, fmaf(x.y, wv.y, acc[u]));
            }
        }
        #pragma unroll
        for (int u = 0; u < 8; u++)
            L2[(r0+u)*DD + tx] = __float2bfloat16(acc[u]);
    }
}

// ---------------- kernel 5: decode via mma.sync (all 200 steps per row) -------
// smem layout (bytes):
//   sQ  [208][136] bf16 @ 0        = 56576   (row-major, padded)
//   sK  [208][136] bf16 @ 56576    = 56576
//   sL  [208][136] bf16 @ 113152   = 56576
//   sV  [128][216] bf16 @ 169728   = 55296   (d-major, padded)
//   sPos int16[256]     @ 225024   = 512
//   sAct int[208]       @ 225536   = 832
//   sLP  float[8]       @ 226368   = 32
#define D_Q   0
#define D_K   56576
#define D_L   113152
#define D_V   169728
#define D_POS 225024
#define D_ACT 225536
#define D_LP  226368
#define DEC_SMEM 226432

__global__ void __launch_bounds__(256,1) k_decode(const int* __restrict__ act_g,
                                                  float* __restrict__ out, int mode){
    extern __shared__ char sm[];
    uint16_t* sQ  = (uint16_t*)(sm + D_Q);
    uint16_t* sK  = (uint16_t*)(sm + D_K);
    uint16_t* sL  = (uint16_t*)(sm + D_L);
    uint16_t* sV  = (uint16_t*)(sm + D_V);
    int16_t*  sPos= (int16_t*)(sm + D_POS);
    int*      sAct= (int*)(sm + D_ACT);
    float*    sLP = (float*)(sm + D_LP);
    int b = blockIdx.x, tid = threadIdx.x;
    int lane = tid & 31, w = tid >> 5;
    int qq = lane & 3, gg = lane >> 2;

    // ---- load & pad ----
    {
        const uint4* gq = (const uint4*)(g_Q  + (size_t)b*AA*DD);
        const uint4* gk = (const uint4*)(g_K  + (size_t)b*AA*DD);
        const uint4* gl = (const uint4*)(g_L2 + (size_t)b*AA*DD);
        const uint4* gv = (const uint4*)(g_VT + (size_t)b*DD*AA);
        uint4 z = make_uint4(0,0,0,0);
        for (int idx = tid; idx < 208*17; idx += 256){
            int r = idx / 17, c = idx % 17;
            bool v = (r < AA) && (c < 16);
            int s = r*16 + c;
            ((uint4*)sQ)[idx] = v ? gq[s] : z;
            ((uint4*)sK)[idx] = v ? gk[s] : z;
            ((uint4*)sL)[idx] = v ? gl[s] : z;
        }
        for (int idx = tid; idx < 128*27; idx += 256){
            int r = idx / 27, c = idx % 27;
            ((uint4*)sV)[idx] = (c < 25) ? gv[r*25 + c] : z;
        }
        for (int idx = tid; idx < 208; idx += 256)
            sAct[idx] = (idx < AA) ? act_g[b*AA + idx] : 0;
        if (tid < 256) sPos[tid] = -1;
        if (tid == 0) { } // nothing
    }
    __syncthreads();
    if (tid < AA) sPos[sAct[tid]] = (int16_t)tid;
    __syncthreads();

    float lp_acc = 0.f;
    #pragma unroll 1
    for (int tile = w; tile < 13; tile += 8){
        int i0 = tile*16;
        int r1 = i0 + gg, r2 = r1 + 8;
        int act1 = sAct[r1], act2 = sAct[r2];
        unsigned long long dead1 = 0, dead2 = 0, sel1 = 0, sel2 = 0;
        #pragma unroll
        for (int nt = 0; nt < 26; nt++){
            #pragma unroll
            for (int e = 0; e < 2; e++){
                int c = nt*8 + qq*2 + e;
                int p = (int)sPos[c];
                unsigned long long bit = 1ull << (nt*2 + e);
                if (p < r1)    dead1 |= bit;
                if (p < r2)    dead2 |= bit;
                if (c == act1) sel1  |= bit;
                if (c == act2) sel2  |= bit;
            }
        }

        uint32_t la[NH][4];
        #pragma unroll
        for (int h = 0; h < NH; h++){
            // Q A-fragment
            uint32_t aq[4];
            aq[0] = *(const uint32_t*)(sQ + r1*136 + h*16 + qq*2);
            aq[1] = *(const uint32_t*)(sQ + r2*136 + h*16 + qq*2);
            aq[2] = *(const uint32_t*)(sQ + r1*136 + h*16 + qq*2 + 8);
            aq[3] = *(const uint32_t*)(sQ + r2*136 + h*16 + qq*2 + 8);
            // S = Q.K^T
            float s[26][4];
            #pragma unroll
            for (int nt = 0; nt < 26; nt++){
                s[nt][0]=0.f; s[nt][1]=0.f; s[nt][2]=0.f; s[nt][3]=0.f;
                const uint16_t* kb = sK + (nt*8 + gg)*136 + h*16 + qq*2;
                uint32_t bb[2];
                bb[0] = *(const uint32_t*)kb;
                bb[1] = *(const uint32_t*)(kb + 8);
                mma16816(s[nt], aq, bb);
            }
            // masked softmax (unnormalized)
            float mx1 = NEG_BIG, mx2 = NEG_BIG;
            #pragma unroll
            for (int nt = 0; nt < 26; nt++){
                #pragma unroll
                for (int e = 0; e < 2; e++){
                    unsigned long long bit = 1ull << (nt*2 + e);
                    if (!(dead1 & bit)) mx1 = fmaxf(mx1, s[nt][e]);
                    if (!(dead2 & bit)) mx2 = fmaxf(mx2, s[nt][2+e]);
                }
            }
            mx1 = qredmax(mx1); mx2 = qredmax(mx2);
            if (mx1 < -1e29f) mx1 = 0.f;
            if (mx2 < -1e29f) mx2 = 0.f;
            float sum1 = 0.f, sum2 = 0.f;
            #pragma unroll
            for (int nt = 0; nt < 26; nt++){
                #pragma unroll
                for (int e = 0; e < 2; e++){
                    unsigned long long bit = 1ull << (nt*2 + e);
                    float w1 = (dead1 & bit) ? 0.f : __expf(s[nt][e]   - mx1);
                    float w2 = (dead2 & bit) ? 0.f : __expf(s[nt][2+e] - mx2);
                    s[nt][e]   = w1; sum1 += w1;
                    s[nt][2+e] = w2; sum2 += w2;
                }
            }
            sum1 = qredsum(sum1); sum2 = qredsum(sum2);
            float inv1 = 1.0f / sum1, inv2 = 1.0f / sum2;
            // heads = P.V  (P packs straight from D-frag into A-frag)
            float hacc[2][4];
            hacc[0][0]=0;hacc[0][1]=0;hacc[0][2]=0;hacc[0][3]=0;
            hacc[1][0]=0;hacc[1][1]=0;hacc[1][2]=0;hacc[1][3]=0;
            #pragma unroll
            for (int kt = 0; kt < 13; kt++){
                uint32_t pa[4];
                pa[0] = pk2(s[2*kt][0],   s[2*kt][1]);
                pa[1] = pk2(s[2*kt][2],   s[2*kt][3]);
                pa[2] = pk2(s[2*kt+1][0], s[2*kt+1][1]);
                pa[3] = pk2(s[2*kt+1][2], s[2*kt+1][3]);
                #pragma unroll
                for (int nv = 0; nv < 2; nv++){
                    const uint16_t* vb = sV + (h*16 + nv*8 + gg)*216 + kt*16 + qq*2;
                    uint32_t bb[2];
                    bb[0] = *(const uint32_t*)vb;
                    bb[1] = *(const uint32_t*)(vb + 8);
                    mma16816(hacc[nv], pa, bb);
                }
            }
            la[h][0] = pk2(hacc[0][0]*inv1, hacc[0][1]*inv1);
            la[h][1] = pk2(hacc[0][2]*inv2, hacc[0][3]*inv2);
            la[h][2] = pk2(hacc[1][0]*inv1, hacc[1][1]*inv1);
            la[h][3] = pk2(hacc[1][2]*inv2, hacc[1][3]*inv2);
        }

        // logits = glimpse . L2^T  (W_out folded into L2)
        float lg[26][4];
        #pragma unroll
        for (int nt = 0; nt < 26; nt++){
            float acc[4] = {0.f, 0.f, 0.f, 0.f};
            #pragma unroll
            for (int h = 0; h < NH; h++){
                const uint16_t* lb = sL + (nt*8 + gg)*136 + h*16 + qq*2;
                uint32_t bb[2];
                bb[0] = *(const uint32_t*)lb;
                bb[1] = *(const uint32_t*)(lb + 8);
                mma16816(acc, la[h], bb);
            }
            #pragma unroll
            for (int e = 0; e < 4; e++){
                float y  = acc[e] * INV_SQRT_D;
                float e2 = __expf(2.0f * y);
                lg[nt][e] = 10.0f - 20.0f / (e2 + 1.0f);   // 10*tanh(y)
            }
        }
        // masked log-softmax + select
        float m1 = NEG_BIG, m2 = NEG_BIG, sv1 = 0.f, sv2 = 0.f;
        #pragma unroll
        for (int nt = 0; nt < 26; nt++){
            #pragma unroll
            for (int e = 0; e < 2; e++){
                unsigned long long bit = 1ull << (nt*2 + e);
                if (!(dead1 & bit)) m1 = fmaxf(m1, lg[nt][e]);
                if (!(dead2 & bit)) m2 = fmaxf(m2, lg[nt][2+e]);
                if (sel1 & bit) sv1 = lg[nt][e];
                if (sel2 & bit) sv2 = lg[nt][2+e];
            }
        }
        m1 = qredmax(m1); m2 = qredmax(m2);
        if (m1 < -1e29f) m1 = 0.f;
        if (m2 < -1e29f) m2 = 0.f;
        float es1 = 0.f, es2 = 0.f;
        #pragma unroll
        for (int nt = 0; nt < 26; nt++){
            #pragma unroll
            for (int e = 0; e < 2; e++){
                unsigned long long bit = 1ull << (nt*2 + e);
                es1 += (dead1 & bit) ? 0.f : __expf(lg[nt][e]   - m1);
                es2 += (dead2 & bit) ? 0.f : __expf(lg[nt][2+e] - m2);
            }
        }
        es1 = qredsum(es1); es2 = qredsum(es2);
        sv1 = qredsum(sv1); sv2 = qredsum(sv2);
        if (qq == 0){
            lp_acc += sv1 - m1 - __logf(es1);          // r1 always < 200
            if (r2 < AA) lp_acc += sv2 - m2 - __logf(es2);
        }
    }

    lp_acc = wredsum(lp_acc);
    if (lane == 0) sLP[w] = lp_acc;
    __syncthreads();
    float* lp_out = mode ? (out + BB*AA) : out;
    if (tid == 0){
        float t = 0.f;
        #pragma unroll
        for (int k = 0; k < 8; k++) t += sLP[k];
        lp_out[b] = t;
    }
    if (mode){
        for (int idx = tid; idx < AA; idx += 256)
            out[b*AA + idx] = (float)sAct[idx];
    }
}

// ---------------- launch -------------------------------------------------------
extern "C" void kernel_launch(void* const* d_in, const int* in_sizes, int n_in,
                              void* d_out, int out_size){
    const float* agent = (const float*)d_in[0];
    const int*   act   = (const int*)d_in[1];
    const float* Wp    = (const float*)d_in[2];
    const float* Wn    = (const float*)d_in[3];
    const float* Wf    = (const float*)d_in[4];
    const float* Ws    = (const float*)d_in[5];
    const float* Wo    = (const float*)d_in[6];
    float* out = (float*)d_out;

    cudaFuncSetAttribute(k_proj,   cudaFuncAttributeMaxDynamicSharedMemorySize, PROJ_SMEM);
    cudaFuncSetAttribute(k_query,  cudaFuncAttributeMaxDynamicSharedMemorySize, QRY_SMEM);
    cudaFuncSetAttribute(k_lk2,    cudaFuncAttributeMaxDynamicSharedMemorySize, LK2_SMEM);
    cudaFuncSetAttribute(k_decode, cudaFuncAttributeMaxDynamicSharedMemorySize, DEC_SMEM);

    k_fixed <<<BB, 128>>>(agent, Wf);
    k_proj  <<<BB, 256, PROJ_SMEM>>>(agent, Wn);
    k_query <<<BB, 256, QRY_SMEM>>>(agent, act, Wp, Ws);
    k_lk2   <<<BB, 256, LK2_SMEM>>>(Wo);

    int mode = (out_size >= BB*AA) ? 1 : 0;
    k_decode<<<BB, 256, DEC_SMEM>>>(act, out, mode);
}

// round 10
// speedup vs baseline: 4.1301x; 2.8161x over previous
#include <cuda_runtime.h>
#include <cuda_bf16.h>
#include <cstdint>

#define BB 1024
#define AA 200
#define DD 128
#define NH 8
#define INV_SQRT_D 0.08838834764831845f

// ---------------- scratch (device globals; no runtime allocation) -------------
__device__ __nv_bfloat16 g_Q [(size_t)BB*AA*DD];   // queries*0.25 row-major [b][i][d]
__device__ __nv_bfloat16 g_K [(size_t)BB*AA*DD];   // gK row-major [b][a][d]
__device__ __nv_bfloat16 g_V [(size_t)BB*AA*DD];   // gV row-major [b][a][d]
__device__ __nv_bfloat16 g_LK[(size_t)BB*AA*DD];   // logit_K row-major [b][a][j]
__device__ __nv_bfloat16 g_L2[(size_t)BB*AA*DD];   // logitK2 row-major [b][a][d]
__device__ __nv_bfloat16 g_Wn[384*136];            // W_node^T padded [n][k]
__device__ __nv_bfloat16 g_Ws[128*136];            // W_step^T padded [j][k]
__device__ __nv_bfloat16 g_Wo[128*136];            // W_out row-major padded [d][j]
__device__ float g_FC[BB*DD];                      // fixed context

// ---------------- helpers ------------------------------------------------------
__device__ __forceinline__ uint16_t f2b(float x){
    return __bfloat16_as_ushort(__float2bfloat16(x));
}
__device__ __forceinline__ uint32_t pk2(float a, float b){
    return (uint32_t)f2b(a) | ((uint32_t)f2b(b) << 16);
}
__device__ __forceinline__ float wredsum(float v){
    #pragma unroll
    for (int o = 16; o; o >>= 1) v += __shfl_xor_sync(0xffffffffu, v, o);
    return v;
}
__device__ __forceinline__ float qredsum(float v){
    v += __shfl_xor_sync(0xffffffffu, v, 1);
    v += __shfl_xor_sync(0xffffffffu, v, 2);
    return v;
}
__device__ __forceinline__ void mma16816(float* d, const uint32_t* a, const uint32_t* b){
    asm volatile(
      "mma.sync.aligned.m16n8k16.row.col.f32.bf16.bf16.f32 "
      "{%0,%1,%2,%3}, {%4,%5,%6,%7}, {%8,%9}, {%0,%1,%2,%3};\n"
      : "+f"(d[0]), "+f"(d[1]), "+f"(d[2]), "+f"(d[3])
      : "r"(a[0]), "r"(a[1]), "r"(a[2]), "r"(a[3]), "r"(b[0]), "r"(b[1]));
}
__device__ __forceinline__ void ldmat_x2_trans(uint32_t& r0, uint32_t& r1, uint32_t addr){
    asm volatile("ldmatrix.sync.aligned.m8n8.x2.trans.shared.b16 {%0,%1}, [%2];"
        : "=r"(r0), "=r"(r1) : "r"(addr));
}

// ---------------- kernel 0: weight prep (convert + transpose + pad) -----------
__global__ void k_prep(const float* __restrict__ Wn, const float* __restrict__ Ws,
                       const float* __restrict__ Wo){
    int t = blockIdx.x*256 + threadIdx.x;
    if (t < 128*384){
        int k = t / 384, n = t - k*384;
        g_Wn[n*136 + k] = __float2bfloat16(Wn[t]);
    }
    if (t < 128*128){
        int k = t >> 7, j = t & 127;
        g_Ws[j*136 + k] = __float2bfloat16(Ws[t]);   // transpose
        g_Wo[k*136 + j] = __float2bfloat16(Wo[t]);   // row-major copy
    }
}

// ---------------- kernel 1: fixed context --------------------------------------
__global__ void k_fixed(const float* __restrict__ agent, const float* __restrict__ Wf){
    int b = blockIdx.x, j = threadIdx.x;
    __shared__ float ge[DD];
    const float* row = agent + (size_t)b*AA*DD;
    float s = 0.f;
    #pragma unroll 4
    for (int a = 0; a < AA; a++) s += row[a*DD + j];
    ge[j] = s * (1.0f/AA);
    __syncthreads();
    float acc = 0.f;
    #pragma unroll 4
    for (int d = 0; d < DD; d++) acc = fmaf(ge[d], Wf[d*DD + j], acc);
    g_FC[b*DD + j] = acc;
}

// ---------------- kernel 2: proj = X @ W_node (mma) -> gK, gV, logit_K --------
#define PROJ_SMEM (56576 + 104448)
__global__ void __launch_bounds__(256,1) k_proj(const float* __restrict__ agent){
    extern __shared__ char sm[];
    uint16_t* sX = (uint16_t*)sm;              // [208][136]
    uint16_t* sW = (uint16_t*)(sm + 56576);    // [384][136]
    int b = blockIdx.x, tid = threadIdx.x;
    {
        const uint4* src = (const uint4*)g_Wn;
        uint4* dst = (uint4*)sW;
        for (int i = tid; i < 384*17; i += 256) dst[i] = src[i];
        const float2* Xg = (const float2*)(agent + (size_t)b*AA*DD);
        uint32_t* dX = (uint32_t*)sX;
        for (int i = tid; i < AA*64; i += 256){
            int r = i >> 6, c = i & 63;
            float2 v = Xg[i];
            dX[r*68 + c] = pk2(v.x, v.y);
        }
        for (int i = 200*68 + tid; i < 208*68; i += 256) dX[i] = 0;
    }
    __syncthreads();
    int lane = tid & 31, w = tid >> 5, qq = lane & 3, gg = lane >> 2;
    __nv_bfloat16* Kr = g_K  + (size_t)b*AA*DD;
    __nv_bfloat16* Vr = g_V  + (size_t)b*AA*DD;
    __nv_bfloat16* Lr = g_LK + (size_t)b*AA*DD;
    #pragma unroll 1
    for (int tile = w; tile < 13; tile += 8){
        int r1 = tile*16 + gg, r2 = r1 + 8;
        uint32_t a[8][4];
        #pragma unroll
        for (int kk = 0; kk < 8; kk++){
            const uint16_t* p1 = sX + r1*136 + kk*16 + qq*2;
            const uint16_t* p2 = sX + r2*136 + kk*16 + qq*2;
            a[kk][0] = *(const uint32_t*)p1;     a[kk][1] = *(const uint32_t*)p2;
            a[kk][2] = *(const uint32_t*)(p1+8); a[kk][3] = *(const uint32_t*)(p2+8);
        }
        #pragma unroll 1
        for (int grp = 0; grp < 3; grp++){
            __nv_bfloat16* dst = (grp == 0) ? Kr : (grp == 1) ? Vr : Lr;
            #pragma unroll 2
            for (int nt = 0; nt < 16; nt++){
                float acc[4] = {0.f,0.f,0.f,0.f};
                const uint16_t* bp = sW + ((grp*16 + nt)*8 + gg)*136 + qq*2;
                #pragma unroll
                for (int kk = 0; kk < 8; kk++){
                    uint32_t bb[2] = { *(const uint32_t*)(bp + kk*16),
                                       *(const uint32_t*)(bp + kk*16 + 8) };
                    mma16816(acc, a[kk], bb);
                }
                int d0 = nt*8 + qq*2;
                if (r1 < AA) *(uint32_t*)(dst + r1*DD + d0) = pk2(acc[0], acc[1]);
                if (r2 < AA) *(uint32_t*)(dst + r2*DD + d0) = pk2(acc[2], acc[3]);
            }
        }
    }
}

// ---------------- kernel 3: queries (mma), pre-scaled by 0.25 ------------------
#define QRY_SMEM (56576 + 34816 + 896)
__global__ void __launch_bounds__(256) k_query(const float* __restrict__ agent,
                                               const int* __restrict__ act_g,
                                               const float* __restrict__ Wp){
    extern __shared__ char sm[];
    uint16_t* sX = (uint16_t*)sm;                      // [208][136]
    uint16_t* sW = (uint16_t*)(sm + 56576);            // [128][136]
    int* sAct = (int*)(sm + 56576 + 34816);
    int b = blockIdx.x, tid = threadIdx.x;
    {
        const uint4* src = (const uint4*)g_Ws;
        uint4* dst = (uint4*)sW;
        for (int i = tid; i < 128*17; i += 256) dst[i] = src[i];
        if (tid < AA) sAct[tid] = act_g[b*AA + tid];
    }
    __syncthreads();
    {
        uint32_t* dX = (uint32_t*)sX;
        for (int i = tid; i < AA*64; i += 256){
            int r = i >> 6, c = i & 63;
            float2 v;
            if (r == 0) v = ((const float2*)Wp)[c];
            else        v = ((const float2*)(agent + ((size_t)b*AA + sAct[r-1])*DD))[c];
            dX[r*68 + c] = pk2(v.x, v.y);
        }
        for (int i = 200*68 + tid; i < 208*68; i += 256) dX[i] = 0;
    }
    __syncthreads();
    int lane = tid & 31, w = tid >> 5, qq = lane & 3, gg = lane >> 2;
    __nv_bfloat16* Qo = g_Q + (size_t)b*AA*DD;
    const float* FC = g_FC + b*DD;
    #pragma unroll 1
    for (int tile = w; tile < 13; tile += 8){
        int r1 = tile*16 + gg, r2 = r1 + 8;
        uint32_t a[8][4];
        #pragma unroll
        for (int kk = 0; kk < 8; kk++){
            const uint16_t* p1 = sX + r1*136 + kk*16 + qq*2;
            const uint16_t* p2 = sX + r2*136 + kk*16 + qq*2;
            a[kk][0] = *(const uint32_t*)p1;     a[kk][1] = *(const uint32_t*)p2;
            a[kk][2] = *(const uint32_t*)(p1+8); a[kk][3] = *(const uint32_t*)(p2+8);
        }
        #pragma unroll 2
        for (int nt = 0; nt < 16; nt++){
            float acc[4] = {0.f,0.f,0.f,0.f};
            const uint16_t* bp = sW + (nt*8 + gg)*136 + qq*2;
            #pragma unroll
            for (int kk = 0; kk < 8; kk++){
                uint32_t bb[2] = { *(const uint32_t*)(bp + kk*16),
                                   *(const uint32_t*)(bp + kk*16 + 8) };
                mma16816(acc, a[kk], bb);
            }
            int d0 = nt*8 + qq*2;
            float2 fc = *(const float2*)(FC + d0);
            if (r1 < AA) *(uint32_t*)(Qo + r1*DD + d0) =
                pk2((fc.x + acc[0])*0.25f, (fc.y + acc[1])*0.25f);
            if (r2 < AA) *(uint32_t*)(Qo + r2*DD + d0) =
                pk2((fc.x + acc[2])*0.25f, (fc.y + acc[3])*0.25f);
        }
    }
}

// ---------------- kernel 4: L2[a][d] = sum_j LK[a][j]*Wo[d][j] (mma) ----------
#define LK2_SMEM (56576 + 34816)
__global__ void __launch_bounds__(256) k_lk2(){
    extern __shared__ char sm[];
    uint16_t* sX = (uint16_t*)sm;
    uint16_t* sW = (uint16_t*)(sm + 56576);
    int b = blockIdx.x, tid = threadIdx.x;
    {
        const uint4* ws = (const uint4*)g_Wo;
        uint4* wd = (uint4*)sW;
        for (int i = tid; i < 128*17; i += 256) wd[i] = ws[i];
        const uint4* xs = (const uint4*)(g_LK + (size_t)b*AA*DD);
        uint4* xd = (uint4*)sX;
        for (int i = tid; i < AA*16; i += 256){
            int r = i >> 4, c = i & 15;
            xd[r*17 + c] = xs[i];
        }
        uint32_t* dX = (uint32_t*)sX;
        for (int i = 200*68 + tid; i < 208*68; i += 256) dX[i] = 0;
    }
    __syncthreads();
    int lane = tid & 31, w = tid >> 5, qq = lane & 3, gg = lane >> 2;
    __nv_bfloat16* L2 = g_L2 + (size_t)b*AA*DD;
    #pragma unroll 1
    for (int tile = w; tile < 13; tile += 8){
        int r1 = tile*16 + gg, r2 = r1 + 8;
        uint32_t a[8][4];
        #pragma unroll
        for (int kk = 0; kk < 8; kk++){
            const uint16_t* p1 = sX + r1*136 + kk*16 + qq*2;
            const uint16_t* p2 = sX + r2*136 + kk*16 + qq*2;
            a[kk][0] = *(const uint32_t*)p1;     a[kk][1] = *(const uint32_t*)p2;
            a[kk][2] = *(const uint32_t*)(p1+8); a[kk][3] = *(const uint32_t*)(p2+8);
        }
        #pragma unroll 2
        for (int nt = 0; nt < 16; nt++){
            float acc[4] = {0.f,0.f,0.f,0.f};
            const uint16_t* bp = sW + (nt*8 + gg)*136 + qq*2;
            #pragma unroll
            for (int kk = 0; kk < 8; kk++){
                uint32_t bb[2] = { *(const uint32_t*)(bp + kk*16),
                                   *(const uint32_t*)(bp + kk*16 + 8) };
                mma16816(acc, a[kk], bb);
            }
            int d0 = nt*8 + qq*2;
            if (r1 < AA) *(uint32_t*)(L2 + r1*DD + d0) = pk2(acc[0], acc[1]);
            if (r2 < AA) *(uint32_t*)(L2 + r2*DD + d0) = pk2(acc[2], acc[3]);
        }
    }
}

// ---------------- kernel 5: decode, streaming mma ------------------------------
#define D_Q   0
#define D_K   56576
#define D_L   113152
#define D_V   169728
#define D_POS 226304
#define D_ACT 226816
#define D_LP  227648
#define DEC_SMEM 227712

__global__ void __launch_bounds__(256,1) k_decode(const int* __restrict__ act_g,
                                                  float* __restrict__ out, int mode){
    extern __shared__ char sm[];
    uint16_t* sQ  = (uint16_t*)(sm + D_Q);
    uint16_t* sK  = (uint16_t*)(sm + D_K);
    uint16_t* sL  = (uint16_t*)(sm + D_L);
    uint16_t* sV  = (uint16_t*)(sm + D_V);
    int16_t*  sPos= (int16_t*)(sm + D_POS);
    int*      sAct= (int*)(sm + D_ACT);
    float*    sLP = (float*)(sm + D_LP);
    int b = blockIdx.x, tid = threadIdx.x;
    int lane = tid & 31, w = tid >> 5, qq = lane & 3, gg = lane >> 2;

    {
        const uint4* gq = (const uint4*)(g_Q  + (size_t)b*AA*DD);
        const uint4* gk = (const uint4*)(g_K  + (size_t)b*AA*DD);
        const uint4* gl = (const uint4*)(g_L2 + (size_t)b*AA*DD);
        const uint4* gv = (const uint4*)(g_V  + (size_t)b*AA*DD);
        uint4 z = make_uint4(0,0,0,0);
        for (int i = tid; i < 208*17; i += 256){
            int r = i / 17, c = i - r*17;
            bool v = (r < AA) && (c < 16);
            int s = r*16 + c;
            ((uint4*)sQ)[i] = v ? gq[s] : z;
            ((uint4*)sK)[i] = v ? gk[s] : z;
            ((uint4*)sL)[i] = v ? gl[s] : z;
            ((uint4*)sV)[i] = v ? gv[s] : z;
        }
        sPos[tid] = -1;
        for (int i = tid; i < 208; i += 256) sAct[i] = (i < AA) ? act_g[b*AA + i] : 0;
    }
    __syncthreads();
    if (tid < AA) sPos[sAct[tid]] = (int16_t)tid;
    __syncthreads();

    uint32_t sVu = (uint32_t)__cvta_generic_to_shared(sV) + (uint32_t)((lane & 15) * 272);

    float lp_acc = 0.f;
    #pragma unroll 1
    for (int tile = w; tile < 13; tile += 8){
        int r1 = tile*16 + gg, r2 = r1 + 8;
        int act1 = sAct[r1], act2 = sAct[r2];
        unsigned long long dead1 = 0, dead2 = 0, sel1 = 0, sel2 = 0;
        #pragma unroll
        for (int nt = 0; nt < 26; nt++){
            #pragma unroll
            for (int e = 0; e < 2; e++){
                int c = nt*8 + qq*2 + e;
                int p = (int)sPos[c];
                unsigned long long bit = 1ull << (nt*2 + e);
                if (p < r1)    dead1 |= bit;
                if (p < r2)    dead2 |= bit;
                if (c == act1) sel1  |= bit;
                if (c == act2) sel2  |= bit;
            }
        }

        uint32_t la[NH][4];
        #pragma unroll
        for (int h = 0; h < NH; h++){
            uint32_t aq[4];
            const uint16_t* q1 = sQ + r1*136 + h*16 + qq*2;
            const uint16_t* q2 = sQ + r2*136 + h*16 + qq*2;
            aq[0] = *(const uint32_t*)q1;     aq[1] = *(const uint32_t*)q2;
            aq[2] = *(const uint32_t*)(q1+8); aq[3] = *(const uint32_t*)(q2+8);
            float sum1 = 0.f, sum2 = 0.f;
            float h0[4] = {0,0,0,0}, h1[4] = {0,0,0,0};
            #pragma unroll 1
            for (int kt = 0; kt < 13; kt++){
                float s0[4] = {0,0,0,0}, s1[4] = {0,0,0,0};
                const uint16_t* kb  = sK + (kt*16 + gg)*136 + h*16 + qq*2;
                const uint16_t* kb2 = kb + 8*136;
                uint32_t b0[2] = { *(const uint32_t*)kb,  *(const uint32_t*)(kb+8)  };
                uint32_t b1[2] = { *(const uint32_t*)kb2, *(const uint32_t*)(kb2+8) };
                mma16816(s0, aq, b0);
                mma16816(s1, aq, b1);
                int sh = kt*4;
                float w00 = ((dead1>>sh)&1)     ? 0.f : __expf(s0[0]);
                float w01 = ((dead1>>(sh+1))&1) ? 0.f : __expf(s0[1]);
                float w02 = ((dead1>>(sh+2))&1) ? 0.f : __expf(s1[0]);
                float w03 = ((dead1>>(sh+3))&1) ? 0.f : __expf(s1[1]);
                float w10 = ((dead2>>sh)&1)     ? 0.f : __expf(s0[2]);
                float w11 = ((dead2>>(sh+1))&1) ? 0.f : __expf(s0[3]);
                float w12 = ((dead2>>(sh+2))&1) ? 0.f : __expf(s1[2]);
                float w13 = ((dead2>>(sh+3))&1) ? 0.f : __expf(s1[3]);
                sum1 += w00 + w01 + w02 + w03;
                sum2 += w10 + w11 + w12 + w13;
                uint32_t pa[4] = { pk2(w00,w01), pk2(w10,w11), pk2(w02,w03), pk2(w12,w13) };
                uint32_t v0, v1;
                uint32_t ad = sVu + (uint32_t)((kt*16*136 + h*16) * 2);
                ldmat_x2_trans(v0, v1, ad);
                { uint32_t bv[2] = {v0, v1}; mma16816(h0, pa, bv); }
                ldmat_x2_trans(v0, v1, ad + 16);
                { uint32_t bv[2] = {v0, v1}; mma16816(h1, pa, bv); }
            }
            sum1 = qredsum(sum1); sum2 = qredsum(sum2);
            float inv1 = 1.0f / sum1;
            float inv2 = (sum2 > 0.f) ? 1.0f / sum2 : 0.f;
            la[h][0] = pk2(h0[0]*inv1, h0[1]*inv1);
            la[h][1] = pk2(h0[2]*inv2, h0[3]*inv2);
            la[h][2] = pk2(h1[0]*inv1, h1[1]*inv1);
            la[h][3] = pk2(h1[2]*inv2, h1[3]*inv2);
        }

        float es1 = 0.f, es2 = 0.f, sv1 = 0.f, sv2 = 0.f;
        #pragma unroll 2
        for (int nt = 0; nt < 26; nt++){
            float acc[4] = {0,0,0,0};
            const uint16_t* lb = sL + (nt*8 + gg)*136 + qq*2;
            #pragma unroll
            for (int h = 0; h < NH; h++){
                uint32_t bb[2] = { *(const uint32_t*)(lb + h*16),
                                   *(const uint32_t*)(lb + h*16 + 8) };
                mma16816(acc, la[h], bb);
            }
            int sh = nt*2;
            #pragma unroll
            for (int e = 0; e < 2; e++){
                float t1 = 10.f - 20.f / (__expf(2.f*INV_SQRT_D*acc[e])   + 1.f);
                float t2 = 10.f - 20.f / (__expf(2.f*INV_SQRT_D*acc[2+e]) + 1.f);
                if (!((dead1>>(sh+e))&1)) es1 += __expf(t1 - 10.f);
                if (!((dead2>>(sh+e))&1)) es2 += __expf(t2 - 10.f);
                if ((sel1>>(sh+e))&1) sv1 = t1;
                if ((sel2>>(sh+e))&1) sv2 = t2;
            }
        }
        es1 = qredsum(es1); es2 = qredsum(es2);
        sv1 = qredsum(sv1); sv2 = qredsum(sv2);
        if (qq == 0){
            lp_acc += sv1 - 10.f - __logf(es1);
            if (r2 < AA) lp_acc += sv2 - 10.f - __logf(es2);
        }
    }

    lp_acc = wredsum(lp_acc);
    if (lane == 0) sLP[w] = lp_acc;
    __syncthreads();
    float* lp_out = mode ? (out + BB*AA) : out;
    if (tid == 0){
        float t = 0.f;
        #pragma unroll
        for (int k = 0; k < 8; k++) t += sLP[k];
        lp_out[b] = t;
    }
    if (mode){
        for (int i = tid; i < AA; i += 256) out[b*AA + i] = (float)sAct[i];
    }
}

// ---------------- launch -------------------------------------------------------
extern "C" void kernel_launch(void* const* d_in, const int* in_sizes, int n_in,
                              void* d_out, int out_size){
    const float* agent = (const float*)d_in[0];
    const int*   act   = (const int*)d_in[1];
    const float* Wp    = (const float*)d_in[2];
    const float* Wn    = (const float*)d_in[3];
    const float* Wf    = (const float*)d_in[4];
    const float* Ws    = (const float*)d_in[5];
    const float* Wo    = (const float*)d_in[6];
    float* out = (float*)d_out;

    cudaFuncSetAttribute(k_proj,   cudaFuncAttributeMaxDynamicSharedMemorySize, PROJ_SMEM);
    cudaFuncSetAttribute(k_query,  cudaFuncAttributeMaxDynamicSharedMemorySize, QRY_SMEM);
    cudaFuncSetAttribute(k_lk2,    cudaFuncAttributeMaxDynamicSharedMemorySize, LK2_SMEM);
    cudaFuncSetAttribute(k_decode, cudaFuncAttributeMaxDynamicSharedMemorySize, DEC_SMEM);

    k_prep  <<<192, 256>>>(Wn, Ws, Wo);
    k_fixed <<<BB, 128>>>(agent, Wf);
    k_proj  <<<BB, 256, PROJ_SMEM>>>(agent);
    k_query <<<BB, 256, QRY_SMEM>>>(agent, act, Wp);
    k_lk2   <<<BB, 256, LK2_SMEM>>>();

    int mode = (out_size >= BB*AA) ? 1 : 0;
    k_decode<<<BB, 256, DEC_SMEM>>>(act, out, mode);
}

// round 11
// speedup vs baseline: 7.6001x; 1.8402x over previous
#include <cuda_runtime.h>
#include <cuda_bf16.h>
#include <cstdint>

#define BB 1024
#define AA 200
#define DD 128
#define NH 8
#define INV_SQRT_D 0.08838834764831845f

// ---------------- small persistent scratch (weights only) ----------------------
__device__ float g_Wc[128*128];      // combined Wn_lk @ Wo^T
__device__ uint2 g_FWs[16*8*32];     // W_step  fragments (pre-scaled by 0.25)
__device__ uint2 g_FWn[32*8*32];     // W_node cols 0..255 (K,V) fragments
__device__ uint2 g_FWc[16*8*32];     // Wc fragments

// ---------------- helpers ------------------------------------------------------
__device__ __forceinline__ uint16_t f2b(float x){
    return __bfloat16_as_ushort(__float2bfloat16(x));
}
__device__ __forceinline__ uint32_t pk2(float a, float b){
    return (uint32_t)f2b(a) | ((uint32_t)f2b(b) << 16);
}
__device__ __forceinline__ float wredsum(float v){
    #pragma unroll
    for (int o = 16; o; o >>= 1) v += __shfl_xor_sync(0xffffffffu, v, o);
    return v;
}
__device__ __forceinline__ float qredsum(float v){
    v += __shfl_xor_sync(0xffffffffu, v, 1);
    v += __shfl_xor_sync(0xffffffffu, v, 2);
    return v;
}
__device__ __forceinline__ void mma16816(float* d, const uint32_t* a, const uint32_t* b){
    asm volatile(
      "mma.sync.aligned.m16n8k16.row.col.f32.bf16.bf16.f32 "
      "{%0,%1,%2,%3}, {%4,%5,%6,%7}, {%8,%9}, {%0,%1,%2,%3};\n"
      : "+f"(d[0]), "+f"(d[1]), "+f"(d[2]), "+f"(d[3])
      : "r"(a[0]), "r"(a[1]), "r"(a[2]), "r"(a[3]), "r"(b[0]), "r"(b[1]));
}
__device__ __forceinline__ void ldmat_x2_trans(uint32_t& r0, uint32_t& r1, uint32_t addr){
    asm volatile("ldmatrix.sync.aligned.m8n8.x2.trans.shared.b16 {%0,%1}, [%2];"
        : "=r"(r0), "=r"(r1) : "r"(addr));
}
__device__ __forceinline__ void mma_chain(float* acc, const uint32_t a[8][4],
                                          const uint2* __restrict__ F, int nt, int lane){
    #pragma unroll
    for (int kk = 0; kk < 8; kk++){
        uint2 u = __ldg(&F[(nt*8 + kk)*32 + lane]);
        uint32_t bb[2] = {u.x, u.y};
        mma16816(acc, a[kk], bb);
    }
}

// ---------------- prep 1: Wc = Wn[:,256:384] @ Wo^T ----------------------------
__global__ void k_prep1(const float* __restrict__ Wn, const float* __restrict__ Wo){
    int t = blockIdx.x*256 + threadIdx.x;      // 64*256 = 16384
    int k = t >> 7, j = t & 127;
    const float* wn = Wn + k*384 + 256;
    const float* wo = Wo + j*128;
    float s = 0.f;
    #pragma unroll 4
    for (int d = 0; d < 128; d++) s = fmaf(wn[d], wo[d], s);
    g_Wc[k*128 + j] = s;
}

// ---------------- prep 2: pack B fragments -------------------------------------
__global__ void k_prep2(const float* __restrict__ Ws, const float* __restrict__ Wn){
    int t = blockIdx.x*256 + threadIdx.x;      // 64*256 = 16384
    int which, id;
    if (t < 4096)       { which = 0; id = t; }
    else if (t < 12288) { which = 1; id = t - 4096; }
    else                { which = 2; id = t - 12288; }
    int lane = id & 31, kk = (id >> 5) & 7, nt = id >> 8;
    int qq = lane & 3, gg = lane >> 2;
    int k0 = kk*16 + qq*2, n = nt*8 + gg;
    float v0, v1, v2, v3;
    if (which == 0){
        v0 = Ws[(k0  )*128 + n]*0.25f; v1 = Ws[(k0+1)*128 + n]*0.25f;
        v2 = Ws[(k0+8)*128 + n]*0.25f; v3 = Ws[(k0+9)*128 + n]*0.25f;
    } else if (which == 1){
        v0 = Wn[(k0  )*384 + n]; v1 = Wn[(k0+1)*384 + n];
        v2 = Wn[(k0+8)*384 + n]; v3 = Wn[(k0+9)*384 + n];
    } else {
        v0 = g_Wc[(k0  )*128 + n]; v1 = g_Wc[(k0+1)*128 + n];
        v2 = g_Wc[(k0+8)*128 + n]; v3 = g_Wc[(k0+9)*128 + n];
    }
    uint2 u; u.x = pk2(v0, v1); u.y = pk2(v2, v3);
    if (which == 0)      g_FWs[id] = u;
    else if (which == 1) g_FWn[id] = u;
    else                 g_FWc[id] = u;
}

// ---------------- fused kernel -------------------------------------------------
// smem regions (bytes):
//  R0 @ 0      : X  -> K (in place)       [208][136] bf16
//  R1 @ 56576  : L2                        [208][136]
//  R2 @ 113152 : V                         [208][136]
//  R3 @ 169728 : Q                         [208][136]
//  sMP @226304 : float[512]
//  sFC @228352 : float[128]
//  sPH @228864 : uint16[144]
//  sPos@229152 : int16[256]
//  sAct@229664 : int[208]
//  sLP @230496 : float[16]
#define F_R0 0
#define F_R1 56576
#define F_R2 113152
#define F_R3 169728
#define F_MP 226304
#define F_FC 228352
#define F_PH 228864
#define F_POS 229152
#define F_ACT 229664
#define F_LP 230496
#define FUSED_SMEM 230560

__global__ void __launch_bounds__(512,1) k_fused(
    const float* __restrict__ agent, const int* __restrict__ act_g,
    const float* __restrict__ Wp, const float* __restrict__ Wf,
    float* __restrict__ out, int mode)
{
    extern __shared__ char sm[];
    uint16_t* sX  = (uint16_t*)(sm + F_R0);   // becomes K
    uint16_t* sL  = (uint16_t*)(sm + F_R1);   // L2
    uint16_t* sV  = (uint16_t*)(sm + F_R2);
    uint16_t* sQ  = (uint16_t*)(sm + F_R3);
    float*    sMP = (float*)(sm + F_MP);
    float*    sFC = (float*)(sm + F_FC);
    uint16_t* sPH = (uint16_t*)(sm + F_PH);
    int16_t*  sPos= (int16_t*)(sm + F_POS);
    int*      sAct= (int*)(sm + F_ACT);
    float*    sLP = (float*)(sm + F_LP);

    int b = blockIdx.x, tid = threadIdx.x;
    int lane = tid & 31, w = tid >> 5, qq = lane & 3, gg = lane >> 2;

    // ---- load X (fp32 -> bf16), PH, act, pos-init ----
    {
        const float2* Xg = (const float2*)(agent + (size_t)b*AA*DD);
        uint32_t* dX = (uint32_t*)sX;
        for (int i = tid; i < AA*64; i += 512){
            int r = i >> 6, c = i & 63;
            float2 v = Xg[i];
            dX[r*68 + c] = pk2(v.x, v.y);
        }
        for (int i = 200*68 + tid; i < 208*68; i += 512) dX[i] = 0;
        if (tid < 144) sPH[tid] = (tid < 128) ? f2b(Wp[tid]) : (uint16_t)0;
        if (tid < 256) sPos[tid] = -1;
        for (int i = tid; i < 208; i += 512) sAct[i] = (i < AA) ? act_g[b*AA + i] : 0;
    }
    __syncthreads();
    if (tid < AA) sPos[sAct[tid]] = (int16_t)tid;
    // ---- FC stage A: column partial sums over agent (fp32, L2-hot) ----
    {
        int part = tid >> 7, j = tid & 127;
        const float* ap = agent + (size_t)b*AA*DD + (size_t)part*50*DD + j;
        float s = 0.f;
        #pragma unroll 5
        for (int r = 0; r < 50; r++) s += ap[r*DD];
        sMP[part*128 + j] = s;
    }
    __syncthreads();
    if (tid < 128)
        sFC[tid] = (sMP[tid] + sMP[128+tid] + sMP[256+tid] + sMP[384+tid]) * (1.0f/AA);
    __syncthreads();
    // ---- FC stage B: mean @ W_fixed (partials), scaled by 0.25 ----
    {
        int q4 = tid >> 7, j = tid & 127;
        float acc = 0.f;
        #pragma unroll 8
        for (int d = q4*32; d < q4*32 + 32; d++) acc = fmaf(sFC[d], Wf[d*128 + j], acc);
        __syncthreads();
        sMP[q4*128 + j] = acc;
    }
    __syncthreads();
    if (tid < 128)
        sFC[tid] = 0.25f*(sMP[tid] + sMP[128+tid] + sMP[256+tid] + sMP[384+tid]);
    __syncthreads();

    int r1 = w*16 + gg, r2 = r1 + 8;

    // ---- Phase Q: gather(X) @ Ws + FC  -> R3 ----
    if (w < 13){
        uint32_t ag[8][4];
        const uint16_t* p1 = (r1 == 0) ? sPH : sX + sAct[r1-1]*136;
        const uint16_t* p2 = sX + sAct[r2-1]*136;
        #pragma unroll
        for (int kk = 0; kk < 8; kk++){
            ag[kk][0] = *(const uint32_t*)(p1 + kk*16 + qq*2);
            ag[kk][1] = *(const uint32_t*)(p2 + kk*16 + qq*2);
            ag[kk][2] = *(const uint32_t*)(p1 + kk*16 + qq*2 + 8);
            ag[kk][3] = *(const uint32_t*)(p2 + kk*16 + qq*2 + 8);
        }
        #pragma unroll 2
        for (int nt = 0; nt < 16; nt++){
            float acc[4] = {0.f,0.f,0.f,0.f};
            mma_chain(acc, ag, g_FWs, nt, lane);
            int d0 = nt*8 + qq*2;
            float2 fc = *(const float2*)(sFC + d0);
            *(uint32_t*)(sQ + r1*136 + d0) = pk2(fc.x + acc[0], fc.y + acc[1]);
            *(uint32_t*)(sQ + r2*136 + d0) = pk2(fc.x + acc[2], fc.y + acc[3]);
        }
    }

    // ---- load own-row A fragments of X (used by L2 and K/V phases) ----
    uint32_t ax[8][4];
    if (w < 13){
        const uint16_t* p1 = sX + r1*136;
        const uint16_t* p2 = sX + r2*136;
        #pragma unroll
        for (int kk = 0; kk < 8; kk++){
            ax[kk][0] = *(const uint32_t*)(p1 + kk*16 + qq*2);
            ax[kk][1] = *(const uint32_t*)(p2 + kk*16 + qq*2);
            ax[kk][2] = *(const uint32_t*)(p1 + kk*16 + qq*2 + 8);
            ax[kk][3] = *(const uint32_t*)(p2 + kk*16 + qq*2 + 8);
        }
        // ---- Phase L2: X @ Wc -> R1 ----
        #pragma unroll 2
        for (int nt = 0; nt < 16; nt++){
            float acc[4] = {0.f,0.f,0.f,0.f};
            mma_chain(acc, ax, g_FWc, nt, lane);
            int d0 = nt*8 + qq*2;
            *(uint32_t*)(sL + r1*136 + d0) = pk2(acc[0], acc[1]);
            *(uint32_t*)(sL + r2*136 + d0) = pk2(acc[2], acc[3]);
        }
    }
    __syncthreads();   // all reads of X complete before in-place K overwrite

    // ---- Phase K/V: X @ Wn[:,0:256]; K overwrites X (own rows), V -> R2 ----
    if (w < 13){
        __syncwarp();
        #pragma unroll 2
        for (int nt = 0; nt < 16; nt++){
            float acc[4] = {0.f,0.f,0.f,0.f};
            mma_chain(acc, ax, g_FWn, nt, lane);
            int d0 = nt*8 + qq*2;
            *(uint32_t*)(sX + r1*136 + d0) = pk2(acc[0], acc[1]);
            *(uint32_t*)(sX + r2*136 + d0) = pk2(acc[2], acc[3]);
        }
        #pragma unroll 2
        for (int nt = 16; nt < 32; nt++){
            float acc[4] = {0.f,0.f,0.f,0.f};
            mma_chain(acc, ax, g_FWn, nt, lane);
            int d0 = (nt - 16)*8 + qq*2;
            *(uint32_t*)(sV + r1*136 + d0) = pk2(acc[0], acc[1]);
            *(uint32_t*)(sV + r2*136 + d0) = pk2(acc[2], acc[3]);
        }
    }
    __syncthreads();

    // ---- decode: tile = w (warps 0..12) ----
    uint32_t sVu = (uint32_t)__cvta_generic_to_shared(sV) + (uint32_t)((lane & 15) * 272);
    float lp_acc = 0.f;
    if (w < 13){
        int act1 = sAct[r1], act2 = sAct[r2];
        unsigned long long dead1 = 0, dead2 = 0, sel1 = 0, sel2 = 0;
        #pragma unroll
        for (int nt = 0; nt < 26; nt++){
            #pragma unroll
            for (int e = 0; e < 2; e++){
                int c = nt*8 + qq*2 + e;
                int p = (int)sPos[c];
                unsigned long long bit = 1ull << (nt*2 + e);
                if (p < r1)    dead1 |= bit;
                if (p < r2)    dead2 |= bit;
                if (c == act1) sel1  |= bit;
                if (c == act2) sel2  |= bit;
            }
        }

        uint32_t la[NH][4];
        #pragma unroll
        for (int h = 0; h < NH; h++){
            uint32_t aq[4];
            const uint16_t* q1 = sQ + r1*136 + h*16 + qq*2;
            const uint16_t* q2 = sQ + r2*136 + h*16 + qq*2;
            aq[0] = *(const uint32_t*)q1;     aq[1] = *(const uint32_t*)q2;
            aq[2] = *(const uint32_t*)(q1+8); aq[3] = *(const uint32_t*)(q2+8);
            float sum1 = 0.f, sum2 = 0.f;
            float h0[4] = {0,0,0,0}, h1[4] = {0,0,0,0};
            #pragma unroll 1
            for (int kt = 0; kt < 13; kt++){
                float s0[4] = {0,0,0,0}, s1[4] = {0,0,0,0};
                const uint16_t* kb  = sX + (kt*16 + gg)*136 + h*16 + qq*2;
                const uint16_t* kb2 = kb + 8*136;
                uint32_t b0[2] = { *(const uint32_t*)kb,  *(const uint32_t*)(kb+8)  };
                uint32_t b1[2] = { *(const uint32_t*)kb2, *(const uint32_t*)(kb2+8) };
                mma16816(s0, aq, b0);
                mma16816(s1, aq, b1);
                int sh = kt*4;
                float w00 = ((dead1>>sh)&1)     ? 0.f : __expf(s0[0]);
                float w01 = ((dead1>>(sh+1))&1) ? 0.f : __expf(s0[1]);
                float w02 = ((dead1>>(sh+2))&1) ? 0.f : __expf(s1[0]);
                float w03 = ((dead1>>(sh+3))&1) ? 0.f : __expf(s1[1]);
                float w10 = ((dead2>>sh)&1)     ? 0.f : __expf(s0[2]);
                float w11 = ((dead2>>(sh+1))&1) ? 0.f : __expf(s0[3]);
                float w12 = ((dead2>>(sh+2))&1) ? 0.f : __expf(s1[2]);
                float w13 = ((dead2>>(sh+3))&1) ? 0.f : __expf(s1[3]);
                sum1 += w00 + w01 + w02 + w03;
                sum2 += w10 + w11 + w12 + w13;
                uint32_t pa[4] = { pk2(w00,w01), pk2(w10,w11), pk2(w02,w03), pk2(w12,w13) };
                uint32_t v0, v1;
                uint32_t ad = sVu + (uint32_t)((kt*16*136 + h*16) * 2);
                ldmat_x2_trans(v0, v1, ad);
                { uint32_t bv[2] = {v0, v1}; mma16816(h0, pa, bv); }
                ldmat_x2_trans(v0, v1, ad + 16);
                { uint32_t bv[2] = {v0, v1}; mma16816(h1, pa, bv); }
            }
            sum1 = qredsum(sum1); sum2 = qredsum(sum2);
            float inv1 = 1.0f / sum1;
            float inv2 = (sum2 > 0.f) ? 1.0f / sum2 : 0.f;
            la[h][0] = pk2(h0[0]*inv1, h0[1]*inv1);
            la[h][1] = pk2(h0[2]*inv2, h0[3]*inv2);
            la[h][2] = pk2(h1[0]*inv1, h1[1]*inv1);
            la[h][3] = pk2(h1[2]*inv2, h1[3]*inv2);
        }

        float es1 = 0.f, es2 = 0.f, sv1 = 0.f, sv2 = 0.f;
        #pragma unroll 2
        for (int nt = 0; nt < 26; nt++){
            float acc[4] = {0,0,0,0};
            const uint16_t* lb = sL + (nt*8 + gg)*136 + qq*2;
            #pragma unroll
            for (int h = 0; h < NH; h++){
                uint32_t bb[2] = { *(const uint32_t*)(lb + h*16),
                                   *(const uint32_t*)(lb + h*16 + 8) };
                mma16816(acc, la[h], bb);
            }
            int sh = nt*2;
            #pragma unroll
            for (int e = 0; e < 2; e++){
                float t1 = 10.f - 20.f / (__expf(2.f*INV_SQRT_D*acc[e])   + 1.f);
                float t2 = 10.f - 20.f / (__expf(2.f*INV_SQRT_D*acc[2+e]) + 1.f);
                if (!((dead1>>(sh+e))&1)) es1 += __expf(t1 - 10.f);
                if (!((dead2>>(sh+e))&1)) es2 += __expf(t2 - 10.f);
                if ((sel1>>(sh+e))&1) sv1 = t1;
                if ((sel2>>(sh+e))&1) sv2 = t2;
            }
        }
        es1 = qredsum(es1); es2 = qredsum(es2);
        sv1 = qredsum(sv1); sv2 = qredsum(sv2);
        if (qq == 0){
            lp_acc += sv1 - 10.f - __logf(es1);
            if (r2 < AA) lp_acc += sv2 - 10.f - __logf(es2);
        }
    }

    lp_acc = wredsum(lp_acc);
    if (lane == 0) sLP[w] = lp_acc;
    __syncthreads();
    float* lp_out = mode ? (out + BB*AA) : out;
    if (tid == 0){
        float t = 0.f;
        #pragma unroll
        for (int k = 0; k < 16; k++) t += sLP[k];
        lp_out[b] = t;
    }
    if (mode){
        for (int i = tid; i < AA; i += 512) out[b*AA + i] = (float)sAct[i];
    }
}

// ---------------- launch -------------------------------------------------------
extern "C" void kernel_launch(void* const* d_in, const int* in_sizes, int n_in,
                              void* d_out, int out_size){
    const float* agent = (const float*)d_in[0];
    const int*   act   = (const int*)d_in[1];
    const float* Wp    = (const float*)d_in[2];
    const float* Wn    = (const float*)d_in[3];
    const float* Wf    = (const float*)d_in[4];
    const float* Ws    = (const float*)d_in[5];
    const float* Wo    = (const float*)d_in[6];
    float* out = (float*)d_out;

    cudaFuncSetAttribute(k_fused, cudaFuncAttributeMaxDynamicSharedMemorySize, FUSED_SMEM);

    k_prep1<<<64, 256>>>(Wn, Wo);
    k_prep2<<<64, 256>>>(Ws, Wn);

    int mode = (out_size >= BB*AA) ? 1 : 0;
    k_fused<<<BB, 512, FUSED_SMEM>>>(agent, act, Wp, Wf, out, mode);
}